// round 1
// baseline (speedup 1.0000x reference)
#include <cuda_runtime.h>
#include <math.h>

#define D_MODEL 2048
#define NHEADS  16
#define DHEAD   128
#define BATCH   64
#define TLEN    128
#define NROWS   (BATCH * TLEN)   // 8192
#define SPAD    129              // padded smem row stride for attention tiles

// ---------------- scratch (allocation-free rule: __device__ globals) ----------------
__device__ float g_Q[(size_t)NROWS * D_MODEL];
__device__ float g_K[(size_t)NROWS * D_MODEL];
__device__ float g_V[(size_t)NROWS * D_MODEL];
__device__ float g_Attn[(size_t)NROWS * D_MODEL];
__device__ float g_cos[TLEN * (DHEAD / 2)];
__device__ float g_sin[TLEN * (DHEAD / 2)];

// ---------------- RoPE table (double precision generation -> exact enough) ----------
__global__ void rope_init_kernel() {
    int idx = blockIdx.x * blockDim.x + threadIdx.x;
    if (idx >= TLEN * 64) return;
    int t = idx >> 6;
    int k = idx & 63;
    // theta_k = 10000^(-2k/128) = exp(-k * ln(10000)/64)
    double theta = exp(-(double)k * (9.210340371976184 / 64.0));
    double ang = (double)t * theta;
    g_cos[idx] = (float)cos(ang);
    g_sin[idx] = (float)sin(ang);
}

// ---------------- GEMM: C[M,N] = A[M,K] @ W[N,K]^T, optional fused RoPE ----------------
// BM=BN=128, BK=16, 256 threads, 8x8 register tile per thread, double-buffered smem.
template <bool ROPE>
__global__ void __launch_bounds__(256, 2)
gemm_nt(const float* __restrict__ A, const float* __restrict__ W,
        float* __restrict__ C, int M, int N, int K) {
    __shared__ float As[2][16][128];   // transposed: As[k][m]
    __shared__ float Bs[2][16][128];   // transposed: Bs[k][n]

    const int tid = threadIdx.x;
    const int tx  = tid & 15;          // 0..15 -> 8 output cols each
    const int ty  = tid >> 4;          // 0..15 -> 8 output rows each

    const float* Ab = A + (size_t)blockIdx.y * 128 * K;
    const float* Wb = W + (size_t)blockIdx.x * 128 * K;

    const int lrow = tid >> 2;         // 0..63
    const int lk   = (tid & 3) << 2;   // 0,4,8,12

    float acc[8][8];
#pragma unroll
    for (int r = 0; r < 8; r++)
#pragma unroll
        for (int c = 0; c < 8; c++) acc[r][c] = 0.0f;

    // preload tile 0
#pragma unroll
    for (int i = 0; i < 2; i++) {
        int r = lrow + i * 64;
        float4 a = *(const float4*)(Ab + (size_t)r * K + lk);
        As[0][lk + 0][r] = a.x; As[0][lk + 1][r] = a.y;
        As[0][lk + 2][r] = a.z; As[0][lk + 3][r] = a.w;
        float4 b = *(const float4*)(Wb + (size_t)r * K + lk);
        Bs[0][lk + 0][r] = b.x; Bs[0][lk + 1][r] = b.y;
        Bs[0][lk + 2][r] = b.z; Bs[0][lk + 3][r] = b.w;
    }
    __syncthreads();

    const int nk = K >> 4;
    float4 pa[2], pb[2];

    for (int kt = 0; kt < nk; kt++) {
        const int buf = kt & 1;
        if (kt + 1 < nk) {
#pragma unroll
            for (int i = 0; i < 2; i++) {
                int r = lrow + i * 64;
                pa[i] = *(const float4*)(Ab + (size_t)r * K + (kt + 1) * 16 + lk);
                pb[i] = *(const float4*)(Wb + (size_t)r * K + (kt + 1) * 16 + lk);
            }
        }
#pragma unroll
        for (int k = 0; k < 16; k++) {
            float ra[8], rb[8];
            *(float4*)&ra[0] = *(const float4*)&As[buf][k][ty * 8];
            *(float4*)&ra[4] = *(const float4*)&As[buf][k][ty * 8 + 4];
            *(float4*)&rb[0] = *(const float4*)&Bs[buf][k][tx * 8];
            *(float4*)&rb[4] = *(const float4*)&Bs[buf][k][tx * 8 + 4];
#pragma unroll
            for (int r = 0; r < 8; r++)
#pragma unroll
                for (int c = 0; c < 8; c++)
                    acc[r][c] = fmaf(ra[r], rb[c], acc[r][c]);
        }
        if (kt + 1 < nk) {
            const int nb = buf ^ 1;
#pragma unroll
            for (int i = 0; i < 2; i++) {
                int r = lrow + i * 64;
                As[nb][lk + 0][r] = pa[i].x; As[nb][lk + 1][r] = pa[i].y;
                As[nb][lk + 2][r] = pa[i].z; As[nb][lk + 3][r] = pa[i].w;
                Bs[nb][lk + 0][r] = pb[i].x; Bs[nb][lk + 1][r] = pb[i].y;
                Bs[nb][lk + 2][r] = pb[i].z; Bs[nb][lk + 3][r] = pb[i].w;
            }
            __syncthreads();
        }
    }

    const int crow = blockIdx.y * 128 + ty * 8;
    const int ccol = blockIdx.x * 128 + tx * 8;

    if (ROPE) {
        // tile cols are head-aligned (128 | blockIdx.x*128), so d = tx*8 + c
#pragma unroll
        for (int r = 0; r < 8; r++) {
            const int t = (crow + r) & (TLEN - 1);
            float out[8];
#pragma unroll
            for (int p = 0; p < 4; p++) {
                const int kidx = tx * 4 + p;         // rotation-pair index within head
                const float cs = g_cos[t * 64 + kidx];
                const float sn = g_sin[t * 64 + kidx];
                const float e = acc[r][2 * p];
                const float o = acc[r][2 * p + 1];
                out[2 * p]     = e * cs - o * sn;
                out[2 * p + 1] = e * sn + o * cs;
            }
            *(float4*)(C + (size_t)(crow + r) * N + ccol)     = *(float4*)&out[0];
            *(float4*)(C + (size_t)(crow + r) * N + ccol + 4) = *(float4*)&out[4];
        }
    } else {
#pragma unroll
        for (int r = 0; r < 8; r++) {
            *(float4*)(C + (size_t)(crow + r) * N + ccol)     = *(float4*)&acc[r][0];
            *(float4*)(C + (size_t)(crow + r) * N + ccol + 4) = *(float4*)&acc[r][4];
        }
    }
}

// ---------------- attention: one CTA per (batch, head) ----------------
// smem: Qs[128][129] + Ks[128][129] + Ss[128][129] = 193.5 KB dynamic
__global__ void __launch_bounds__(256)
attn_kernel(const float* __restrict__ Q, const float* __restrict__ K,
            const float* __restrict__ V, float* __restrict__ O) {
    extern __shared__ float sm[];
    float* Qs = sm;                    // [t][d], also reused for V later
    float* Ks = sm + 128 * SPAD;
    float* Ss = sm + 2 * 128 * SPAD;   // scores / probs [q][k]

    const int bh = blockIdx.x;
    const int b = bh >> 4;
    const int h = bh & 15;
    const size_t base = (size_t)b * TLEN * D_MODEL + (size_t)h * DHEAD;
    const float* Qg = Q + base;
    const float* Kg = K + base;
    const float* Vg = V + base;
    float* Og = O + base;

    const int tid = threadIdx.x;
    const int tx = tid & 15, ty = tid >> 4;

    // load Q, K tiles (coalesced reads; padded smem rows -> conflict-free writes)
    for (int idx = tid; idx < 128 * 128; idx += 256) {
        int t = idx >> 7, d = idx & 127;
        Qs[t * SPAD + d] = Qg[(size_t)t * D_MODEL + d];
        Ks[t * SPAD + d] = Kg[(size_t)t * D_MODEL + d];
    }
    __syncthreads();

    // S = Q K^T / sqrt(128), causal-masked
    {
        float acc[8][8];
#pragma unroll
        for (int r = 0; r < 8; r++)
#pragma unroll
            for (int c = 0; c < 8; c++) acc[r][c] = 0.0f;

        for (int k = 0; k < 128; k++) {
            float ra[8], rb[8];
#pragma unroll
            for (int r = 0; r < 8; r++) ra[r] = Qs[(ty * 8 + r) * SPAD + k];
#pragma unroll
            for (int c = 0; c < 8; c++) rb[c] = Ks[(tx * 8 + c) * SPAD + k];
#pragma unroll
            for (int r = 0; r < 8; r++)
#pragma unroll
                for (int c = 0; c < 8; c++)
                    acc[r][c] = fmaf(ra[r], rb[c], acc[r][c]);
        }
        const float scale = 0.08838834764831845f;  // 1/sqrt(128)
#pragma unroll
        for (int r = 0; r < 8; r++) {
            int i = ty * 8 + r;
#pragma unroll
            for (int c = 0; c < 8; c++) {
                int j = tx * 8 + c;
                Ss[i * SPAD + j] = (j <= i) ? acc[r][c] * scale : -1.0e30f;
            }
        }
    }
    __syncthreads();

    // load V into Qs slot; softmax rows in-place (each warp owns 16 rows)
    for (int idx = tid; idx < 128 * 128; idx += 256) {
        int t = idx >> 7, d = idx & 127;
        Qs[t * SPAD + d] = Vg[(size_t)t * D_MODEL + d];
    }
    {
        const int wid = tid >> 5, lane = tid & 31;
        for (int i = wid * 16; i < wid * 16 + 16; i++) {
            float v[4], m = -1.0e30f;
#pragma unroll
            for (int q = 0; q < 4; q++) {
                v[q] = Ss[i * SPAD + lane + q * 32];
                m = fmaxf(m, v[q]);
            }
#pragma unroll
            for (int off = 16; off > 0; off >>= 1)
                m = fmaxf(m, __shfl_xor_sync(0xffffffffu, m, off));
            float s = 0.0f;
#pragma unroll
            for (int q = 0; q < 4; q++) { v[q] = __expf(v[q] - m); s += v[q]; }
#pragma unroll
            for (int off = 16; off > 0; off >>= 1)
                s += __shfl_xor_sync(0xffffffffu, s, off);
            float inv = 1.0f / s;
#pragma unroll
            for (int q = 0; q < 4; q++)
                Ss[i * SPAD + lane + q * 32] = v[q] * inv;
        }
    }
    __syncthreads();

    // O = P @ V
    {
        float o[8][8];
#pragma unroll
        for (int r = 0; r < 8; r++)
#pragma unroll
            for (int c = 0; c < 8; c++) o[r][c] = 0.0f;

        for (int j = 0; j < 128; j++) {
            float rp[8], rv[8];
#pragma unroll
            for (int r = 0; r < 8; r++) rp[r] = Ss[(ty * 8 + r) * SPAD + j];
#pragma unroll
            for (int c = 0; c < 8; c++) rv[c] = Qs[j * SPAD + tx * 8 + c];
#pragma unroll
            for (int r = 0; r < 8; r++)
#pragma unroll
                for (int c = 0; c < 8; c++)
                    o[r][c] = fmaf(rp[r], rv[c], o[r][c]);
        }
#pragma unroll
        for (int r = 0; r < 8; r++) {
            *(float4*)(Og + (size_t)(ty * 8 + r) * D_MODEL + tx * 8)     = *(float4*)&o[r][0];
            *(float4*)(Og + (size_t)(ty * 8 + r) * D_MODEL + tx * 8 + 4) = *(float4*)&o[r][4];
        }
    }
}

// ---------------- launch ----------------
extern "C" void kernel_launch(void* const* d_in, const int* in_sizes, int n_in,
                              void* d_out, int out_size) {
    const float* x  = (const float*)d_in[0];
    const float* WQ = (const float*)d_in[1];
    const float* WK = (const float*)d_in[2];
    const float* WV = (const float*)d_in[3];
    const float* WO = (const float*)d_in[4];
    // d_in[5] = mask (ignored; causal structure is hardcoded)
    float* out = (float*)d_out;

    static float *pQ = nullptr, *pK = nullptr, *pV = nullptr, *pA = nullptr;
    static bool inited = false;
    if (!inited) {
        cudaGetSymbolAddress((void**)&pQ, g_Q);
        cudaGetSymbolAddress((void**)&pK, g_K);
        cudaGetSymbolAddress((void**)&pV, g_V);
        cudaGetSymbolAddress((void**)&pA, g_Attn);
        cudaFuncSetAttribute(attn_kernel,
                             cudaFuncAttributeMaxDynamicSharedMemorySize,
                             3 * 128 * SPAD * sizeof(float));
        inited = true;
    }

    rope_init_kernel<<<32, 256>>>();

    dim3 grid(D_MODEL / 128, NROWS / 128);   // (16, 64)
    dim3 blk(256);
    gemm_nt<true ><<<grid, blk>>>(x, WQ, pQ, NROWS, D_MODEL, D_MODEL);
    gemm_nt<true ><<<grid, blk>>>(x, WK, pK, NROWS, D_MODEL, D_MODEL);
    gemm_nt<false><<<grid, blk>>>(x, WV, pV, NROWS, D_MODEL, D_MODEL);

    attn_kernel<<<BATCH * NHEADS, 256, 3 * 128 * SPAD * sizeof(float)>>>(pQ, pK, pV, pA);

    gemm_nt<false><<<grid, blk>>>(pA, WO, out, NROWS, D_MODEL, D_MODEL);
}

// round 3
// speedup vs baseline: 1.5917x; 1.5917x over previous
#include <cuda_runtime.h>
#include <cuda_bf16.h>
#include <cstdint>
#include <math.h>

#define D_MODEL 2048
#define NHEADS  16
#define DHEAD   128
#define BATCH   64
#define TLEN    128
#define NROWS   (BATCH * TLEN)   // 8192
#define SPAD    129

// ---------------- scratch ----------------
__device__ float g_Q[(size_t)NROWS * D_MODEL];
__device__ float g_K[(size_t)NROWS * D_MODEL];
__device__ float g_V[(size_t)NROWS * D_MODEL];
__device__ float g_Attn[(size_t)NROWS * D_MODEL];
__device__ float g_cos[TLEN * (DHEAD / 2)];
__device__ float g_sin[TLEN * (DHEAD / 2)];

// ---------------- RoPE table ----------------
__global__ void rope_init_kernel() {
    int idx = blockIdx.x * blockDim.x + threadIdx.x;
    if (idx >= TLEN * 64) return;
    int t = idx >> 6;
    int k = idx & 63;
    double theta = exp(-(double)k * (9.210340371976184 / 64.0));
    double ang = (double)t * theta;
    g_cos[idx] = (float)cos(ang);
    g_sin[idx] = (float)sin(ang);
}

// ---------------- mma/ldmatrix primitives (sm_80+ PTX, no 'a' target needed) ----------
__device__ __forceinline__ void mma16816(float* c, const uint32_t* a, const uint32_t* b) {
    asm volatile(
        "mma.sync.aligned.m16n8k16.row.col.f32.bf16.bf16.f32 "
        "{%0,%1,%2,%3}, {%4,%5,%6,%7}, {%8,%9}, {%0,%1,%2,%3};"
        : "+f"(c[0]), "+f"(c[1]), "+f"(c[2]), "+f"(c[3])
        : "r"(a[0]), "r"(a[1]), "r"(a[2]), "r"(a[3]), "r"(b[0]), "r"(b[1]));
}
__device__ __forceinline__ void ldmx4(uint32_t* r, uint32_t addr) {
    asm volatile("ldmatrix.sync.aligned.m8n8.x4.shared.b16 {%0,%1,%2,%3}, [%4];"
                 : "=r"(r[0]), "=r"(r[1]), "=r"(r[2]), "=r"(r[3]) : "r"(addr));
}
__device__ __forceinline__ uint32_t smem_u32(const void* p) {
    return (uint32_t)__cvta_generic_to_shared(p);
}

// ---------------- tcgen05-free tensor GEMM: C[M,N] = A[M,K] @ W[N,K]^T ----------------
// bf16x3 split. CTA tile 128x128, BK=32, 8 warps (2x4), warp tile 64x32.
// SMEM planes per stage (row stride 40 bf16 = 80B, 16B-aligned, ldmatrix conflict-free):
//   Ahi, Alo, Bhi, Blo : 128 rows x 80B = 10240B each -> 40960B/stage, 2 stages.
#define RSTRIDE     40                       // bf16 elements per smem row
#define PLANE_B     (128 * RSTRIDE * 2)      // 10240 bytes
#define STAGE_B     (4 * PLANE_B)            // 40960
#define GEMM_SMEM   (2 * STAGE_B)            // 81920

__device__ __forceinline__ void split4(float4 v, uint2& hi, uint2& lo) {
    __nv_bfloat162 h01 = __floats2bfloat162_rn(v.x, v.y);
    __nv_bfloat162 h23 = __floats2bfloat162_rn(v.z, v.w);
    float lx = v.x - __bfloat162float(h01.x);
    float ly = v.y - __bfloat162float(h01.y);
    float lz = v.z - __bfloat162float(h23.x);
    float lw = v.w - __bfloat162float(h23.y);
    __nv_bfloat162 l01 = __floats2bfloat162_rn(lx, ly);
    __nv_bfloat162 l23 = __floats2bfloat162_rn(lz, lw);
    hi.x = *(uint32_t*)&h01; hi.y = *(uint32_t*)&h23;
    lo.x = *(uint32_t*)&l01; lo.y = *(uint32_t*)&l23;
}

template <bool ROPE>
__global__ void __launch_bounds__(256, 1)
gemm_tc(const float* __restrict__ A, const float* __restrict__ W,
        float* __restrict__ C, int M, int N, int K) {
    extern __shared__ char smem[];
    const uint32_t sb = smem_u32(smem);

    const int tid  = threadIdx.x;
    const int wid  = tid >> 5;
    const int lane = tid & 31;
    const int warp_m = (wid >> 2) * 64;   // 0 or 64
    const int warp_n = (wid & 3) * 32;    // 0,32,64,96

    const float* Ab = A + (size_t)blockIdx.y * 128 * K;
    const float* Wb = W + (size_t)blockIdx.x * 128 * K;

    // loader mapping: 1024 float4 slots per operand tile (128 rows x 8 float4)
    const int lrow = tid >> 3;        // rows covered in 4 iters: +32 each
    const int lc4  = tid & 7;

    // ldmatrix per-lane base offsets (bytes within a plane)
    const uint32_t a_off = (uint32_t)(warp_m + (lane & 15)) * 80u + ((lane >> 4) * 8u) * 2u;
    const uint32_t b_row = (uint32_t)(warp_n + (lane & 7) + ((lane >> 4) & 1) * 8);
    const uint32_t b_off = b_row * 80u + (((lane >> 3) & 1) * 8u) * 2u;

    float acc[4][4][4];
#pragma unroll
    for (int i = 0; i < 4; i++)
#pragma unroll
        for (int j = 0; j < 4; j++)
#pragma unroll
            for (int q = 0; q < 4; q++) acc[i][j][q] = 0.0f;

    const int NCHUNK = K >> 5;   // 64 chunks of BK=32

    // ---- preload chunk 0 into regs, store to stage 0 ----
    float4 pa[4], pb[4];
#pragma unroll
    for (int i = 0; i < 4; i++) {
        const int r = lrow + i * 32;
        pa[i] = *(const float4*)(Ab + (size_t)r * K + lc4 * 4);
        pb[i] = *(const float4*)(Wb + (size_t)r * K + lc4 * 4);
    }
    {
        char* st = smem;
#pragma unroll
        for (int i = 0; i < 4; i++) {
            const int r = lrow + i * 32;
            const uint32_t o = (uint32_t)r * 80u + (uint32_t)lc4 * 8u;
            uint2 hi, lo;
            split4(pa[i], hi, lo);
            *(uint2*)(st + o) = hi;
            *(uint2*)(st + PLANE_B + o) = lo;
            split4(pb[i], hi, lo);
            *(uint2*)(st + 2 * PLANE_B + o) = hi;
            *(uint2*)(st + 3 * PLANE_B + o) = lo;
        }
    }
    __syncthreads();

    for (int ki = 0; ki < NCHUNK; ki++) {
        const uint32_t stage = sb + (uint32_t)(ki & 1) * STAGE_B;

        // prefetch next chunk
        if (ki + 1 < NCHUNK) {
            const int kofs = (ki + 1) * 32;
#pragma unroll
            for (int i = 0; i < 4; i++) {
                const int r = lrow + i * 32;
                pa[i] = *(const float4*)(Ab + (size_t)r * K + kofs + lc4 * 4);
                pb[i] = *(const float4*)(Wb + (size_t)r * K + kofs + lc4 * 4);
            }
        }

        // compute on current stage: 2 k-steps of 16
#pragma unroll
        for (int ks = 0; ks < 2; ks++) {
            const uint32_t kbyte = (uint32_t)ks * 32u;
            uint32_t ah[4][4], al[4][4], bh[4][2], bl[4][2];
#pragma unroll
            for (int mt = 0; mt < 4; mt++) {
                ldmx4(ah[mt], stage + a_off + (uint32_t)mt * (16u * 80u) + kbyte);
                ldmx4(al[mt], stage + PLANE_B + a_off + (uint32_t)mt * (16u * 80u) + kbyte);
            }
#pragma unroll
            for (int np = 0; np < 2; np++) {
                uint32_t t[4];
                ldmx4(t, stage + 2 * PLANE_B + b_off + (uint32_t)np * (16u * 80u) + kbyte);
                bh[2 * np][0] = t[0]; bh[2 * np][1] = t[1];
                bh[2 * np + 1][0] = t[2]; bh[2 * np + 1][1] = t[3];
                ldmx4(t, stage + 3 * PLANE_B + b_off + (uint32_t)np * (16u * 80u) + kbyte);
                bl[2 * np][0] = t[0]; bl[2 * np][1] = t[1];
                bl[2 * np + 1][0] = t[2]; bl[2 * np + 1][1] = t[3];
            }
#pragma unroll
            for (int mt = 0; mt < 4; mt++)
#pragma unroll
                for (int nt = 0; nt < 4; nt++) {
                    mma16816(acc[mt][nt], ah[mt], bh[nt]);
                    mma16816(acc[mt][nt], ah[mt], bl[nt]);
                    mma16816(acc[mt][nt], al[mt], bh[nt]);
                }
        }

        // store prefetched chunk into the other stage
        if (ki + 1 < NCHUNK) {
            __syncthreads();
            char* st = smem + ((ki + 1) & 1) * STAGE_B;
#pragma unroll
            for (int i = 0; i < 4; i++) {
                const int r = lrow + i * 32;
                const uint32_t o = (uint32_t)r * 80u + (uint32_t)lc4 * 8u;
                uint2 hi, lo;
                split4(pa[i], hi, lo);
                *(uint2*)(st + o) = hi;
                *(uint2*)(st + PLANE_B + o) = lo;
                split4(pb[i], hi, lo);
                *(uint2*)(st + 2 * PLANE_B + o) = hi;
                *(uint2*)(st + 3 * PLANE_B + o) = lo;
            }
            __syncthreads();
        }
    }

    // ---- epilogue: registers -> C, RoPE fused for Q/K ----
    const int rbase = blockIdx.y * 128 + warp_m + (lane >> 2);
    const int cbase = blockIdx.x * 128 + warp_n + (lane & 3) * 2;
#pragma unroll
    for (int mt = 0; mt < 4; mt++) {
#pragma unroll
        for (int half = 0; half < 2; half++) {
            const int grow = rbase + mt * 16 + half * 8;
            const int t = grow & (TLEN - 1);
            float* Cr = C + (size_t)grow * N;
#pragma unroll
            for (int nt = 0; nt < 4; nt++) {
                const int gcol = cbase + nt * 8;
                float e = acc[mt][nt][half * 2 + 0];
                float o = acc[mt][nt][half * 2 + 1];
                if (ROPE) {
                    const int kidx = (gcol & 127) >> 1;
                    const float cs = g_cos[t * 64 + kidx];
                    const float sn = g_sin[t * 64 + kidx];
                    const float e2 = e * cs - o * sn;
                    o = e * sn + o * cs;
                    e = e2;
                }
                float2 v; v.x = e; v.y = o;
                *(float2*)(Cr + gcol) = v;
            }
        }
    }
}

// ---------------- attention: one CTA per (batch, head), fp32 ----------------
__global__ void __launch_bounds__(256)
attn_kernel(const float* __restrict__ Q, const float* __restrict__ K,
            const float* __restrict__ V, float* __restrict__ O) {
    extern __shared__ float sm[];
    float* Qs = sm;
    float* Ks = sm + 128 * SPAD;
    float* Ss = sm + 2 * 128 * SPAD;

    const int bh = blockIdx.x;
    const int b = bh >> 4;
    const int h = bh & 15;
    const size_t base = (size_t)b * TLEN * D_MODEL + (size_t)h * DHEAD;
    const float* Qg = Q + base;
    const float* Kg = K + base;
    const float* Vg = V + base;
    float* Og = O + base;

    const int tid = threadIdx.x;
    const int tx = tid & 15, ty = tid >> 4;

    for (int idx = tid; idx < 128 * 128; idx += 256) {
        int t = idx >> 7, d = idx & 127;
        Qs[t * SPAD + d] = Qg[(size_t)t * D_MODEL + d];
        Ks[t * SPAD + d] = Kg[(size_t)t * D_MODEL + d];
    }
    __syncthreads();

    {
        float acc[8][8];
#pragma unroll
        for (int r = 0; r < 8; r++)
#pragma unroll
            for (int c = 0; c < 8; c++) acc[r][c] = 0.0f;

        for (int k = 0; k < 128; k++) {
            float ra[8], rb[8];
#pragma unroll
            for (int r = 0; r < 8; r++) ra[r] = Qs[(ty * 8 + r) * SPAD + k];
#pragma unroll
            for (int c = 0; c < 8; c++) rb[c] = Ks[(tx * 8 + c) * SPAD + k];
#pragma unroll
            for (int r = 0; r < 8; r++)
#pragma unroll
                for (int c = 0; c < 8; c++)
                    acc[r][c] = fmaf(ra[r], rb[c], acc[r][c]);
        }
        const float scale = 0.08838834764831845f;
#pragma unroll
        for (int r = 0; r < 8; r++) {
            int i = ty * 8 + r;
#pragma unroll
            for (int c = 0; c < 8; c++) {
                int j = tx * 8 + c;
                Ss[i * SPAD + j] = (j <= i) ? acc[r][c] * scale : -1.0e30f;
            }
        }
    }
    __syncthreads();

    for (int idx = tid; idx < 128 * 128; idx += 256) {
        int t = idx >> 7, d = idx & 127;
        Qs[t * SPAD + d] = Vg[(size_t)t * D_MODEL + d];
    }
    {
        const int wid = tid >> 5, lane = tid & 31;
        for (int i = wid * 16; i < wid * 16 + 16; i++) {
            float v[4], m = -1.0e30f;
#pragma unroll
            for (int q = 0; q < 4; q++) {
                v[q] = Ss[i * SPAD + lane + q * 32];
                m = fmaxf(m, v[q]);
            }
#pragma unroll
            for (int off = 16; off > 0; off >>= 1)
                m = fmaxf(m, __shfl_xor_sync(0xffffffffu, m, off));
            float s = 0.0f;
#pragma unroll
            for (int q = 0; q < 4; q++) { v[q] = __expf(v[q] - m); s += v[q]; }
#pragma unroll
            for (int off = 16; off > 0; off >>= 1)
                s += __shfl_xor_sync(0xffffffffu, s, off);
            float inv = 1.0f / s;
#pragma unroll
            for (int q = 0; q < 4; q++)
                Ss[i * SPAD + lane + q * 32] = v[q] * inv;
        }
    }
    __syncthreads();

    {
        float o[8][8];
#pragma unroll
        for (int r = 0; r < 8; r++)
#pragma unroll
            for (int c = 0; c < 8; c++) o[r][c] = 0.0f;

        for (int j = 0; j < 128; j++) {
            float rp[8], rv[8];
#pragma unroll
            for (int r = 0; r < 8; r++) rp[r] = Ss[(ty * 8 + r) * SPAD + j];
#pragma unroll
            for (int c = 0; c < 8; c++) rv[c] = Qs[j * SPAD + tx * 8 + c];
#pragma unroll
            for (int r = 0; r < 8; r++)
#pragma unroll
                for (int c = 0; c < 8; c++)
                    o[r][c] = fmaf(rp[r], rv[c], o[r][c]);
        }
#pragma unroll
        for (int r = 0; r < 8; r++) {
            *(float4*)(Og + (size_t)(ty * 8 + r) * D_MODEL + tx * 8)     = *(float4*)&o[r][0];
            *(float4*)(Og + (size_t)(ty * 8 + r) * D_MODEL + tx * 8 + 4) = *(float4*)&o[r][4];
        }
    }
}

// ---------------- launch ----------------
extern "C" void kernel_launch(void* const* d_in, const int* in_sizes, int n_in,
                              void* d_out, int out_size) {
    const float* x  = (const float*)d_in[0];
    const float* WQ = (const float*)d_in[1];
    const float* WK = (const float*)d_in[2];
    const float* WV = (const float*)d_in[3];
    const float* WO = (const float*)d_in[4];
    float* out = (float*)d_out;

    static float *pQ = nullptr, *pK = nullptr, *pV = nullptr, *pA = nullptr;
    static bool inited = false;
    if (!inited) {
        cudaGetSymbolAddress((void**)&pQ, g_Q);
        cudaGetSymbolAddress((void**)&pK, g_K);
        cudaGetSymbolAddress((void**)&pV, g_V);
        cudaGetSymbolAddress((void**)&pA, g_Attn);
        cudaFuncSetAttribute(attn_kernel,
                             cudaFuncAttributeMaxDynamicSharedMemorySize,
                             3 * 128 * SPAD * sizeof(float));
        cudaFuncSetAttribute(gemm_tc<true>,
                             cudaFuncAttributeMaxDynamicSharedMemorySize, GEMM_SMEM);
        cudaFuncSetAttribute(gemm_tc<false>,
                             cudaFuncAttributeMaxDynamicSharedMemorySize, GEMM_SMEM);
        inited = true;
    }

    rope_init_kernel<<<32, 256>>>();

    dim3 grid(D_MODEL / 128, NROWS / 128);   // (16, 64)
    dim3 blk(256);
    gemm_tc<true ><<<grid, blk, GEMM_SMEM>>>(x, WQ, pQ, NROWS, D_MODEL, D_MODEL);
    gemm_tc<true ><<<grid, blk, GEMM_SMEM>>>(x, WK, pK, NROWS, D_MODEL, D_MODEL);
    gemm_tc<false><<<grid, blk, GEMM_SMEM>>>(x, WV, pV, NROWS, D_MODEL, D_MODEL);

    attn_kernel<<<BATCH * NHEADS, 256, 3 * 128 * SPAD * sizeof(float)>>>(pQ, pK, pV, pA);

    gemm_tc<false><<<grid, blk, GEMM_SMEM>>>(pA, WO, out, NROWS, D_MODEL, D_MODEL);
}

// round 4
// speedup vs baseline: 2.8782x; 1.8083x over previous
#include <cuda_runtime.h>
#include <cuda_bf16.h>
#include <cstdint>
#include <math.h>

#define D_MODEL 2048
#define NHEADS  16
#define DHEAD   128
#define BATCH   64
#define TLEN    128
#define NROWS   (BATCH * TLEN)   // 8192

typedef __nv_bfloat16 bf16;
typedef uint32_t u32;

// ---------------- bf16 hi/lo plane scratch ----------------
__device__ bf16 g_xhi[(size_t)NROWS * D_MODEL];
__device__ bf16 g_xlo[(size_t)NROWS * D_MODEL];
__device__ bf16 g_qhi[(size_t)NROWS * D_MODEL];
__device__ bf16 g_qlo[(size_t)NROWS * D_MODEL];
__device__ bf16 g_khi[(size_t)NROWS * D_MODEL];
__device__ bf16 g_klo[(size_t)NROWS * D_MODEL];
__device__ bf16 g_vhi[(size_t)NROWS * D_MODEL];
__device__ bf16 g_vlo[(size_t)NROWS * D_MODEL];
__device__ bf16 g_ahi[(size_t)NROWS * D_MODEL];
__device__ bf16 g_alo[(size_t)NROWS * D_MODEL];
__device__ bf16 g_wqhi[(size_t)D_MODEL * D_MODEL];
__device__ bf16 g_wqlo[(size_t)D_MODEL * D_MODEL];
__device__ bf16 g_wkhi[(size_t)D_MODEL * D_MODEL];
__device__ bf16 g_wklo[(size_t)D_MODEL * D_MODEL];
__device__ bf16 g_wvhi[(size_t)D_MODEL * D_MODEL];
__device__ bf16 g_wvlo[(size_t)D_MODEL * D_MODEL];
__device__ bf16 g_wohi[(size_t)D_MODEL * D_MODEL];
__device__ bf16 g_wolo[(size_t)D_MODEL * D_MODEL];
__device__ float g_cos[TLEN * 64];
__device__ float g_sin[TLEN * 64];

// ---------------- primitives ----------------
__device__ __forceinline__ void mma16816(float* c, const u32* a, const u32* b) {
    asm volatile(
        "mma.sync.aligned.m16n8k16.row.col.f32.bf16.bf16.f32 "
        "{%0,%1,%2,%3}, {%4,%5,%6,%7}, {%8,%9}, {%0,%1,%2,%3};"
        : "+f"(c[0]), "+f"(c[1]), "+f"(c[2]), "+f"(c[3])
        : "r"(a[0]), "r"(a[1]), "r"(a[2]), "r"(a[3]), "r"(b[0]), "r"(b[1]));
}
__device__ __forceinline__ void ldmx4(u32* r, u32 addr) {
    asm volatile("ldmatrix.sync.aligned.m8n8.x4.shared.b16 {%0,%1,%2,%3}, [%4];"
                 : "=r"(r[0]), "=r"(r[1]), "=r"(r[2]), "=r"(r[3]) : "r"(addr));
}
__device__ __forceinline__ void ldmx4t(u32* r, u32 addr) {
    asm volatile("ldmatrix.sync.aligned.m8n8.x4.trans.shared.b16 {%0,%1,%2,%3}, [%4];"
                 : "=r"(r[0]), "=r"(r[1]), "=r"(r[2]), "=r"(r[3]) : "r"(addr));
}
__device__ __forceinline__ u32 smem_u32(const void* p) {
    return (u32)__cvta_generic_to_shared(p);
}
#define CP_ASYNC16(dst, src) \
    asm volatile("cp.async.cg.shared.global [%0], [%1], 16;" :: "r"(dst), "l"(src))
#define CP_COMMIT() asm volatile("cp.async.commit_group;" ::: "memory")
#define CP_WAIT(n)  asm volatile("cp.async.wait_group %0;" :: "n"(n) : "memory")

__device__ __forceinline__ u32 packbf(bf16 a, bf16 b) {
    __nv_bfloat162 h; h.x = a; h.y = b;
    return *(u32*)&h;
}
__device__ __forceinline__ void split2(float e, float o, u32& hi, u32& lo) {
    bf16 eh = __float2bfloat16_rn(e);
    bf16 oh = __float2bfloat16_rn(o);
    float er = e - __bfloat162float(eh);
    float orr = o - __bfloat162float(oh);
    hi = packbf(eh, oh);
    lo = packbf(__float2bfloat16_rn(er), __float2bfloat16_rn(orr));
}

// ---------------- RoPE table ----------------
__global__ void rope_init_kernel() {
    int idx = blockIdx.x * blockDim.x + threadIdx.x;
    if (idx >= TLEN * 64) return;
    int t = idx >> 6;
    int k = idx & 63;
    double theta = exp(-(double)k * (9.210340371976184 / 64.0));
    double ang = (double)t * theta;
    g_cos[idx] = (float)cos(ang);
    g_sin[idx] = (float)sin(ang);
}

// ---------------- split fp32 -> bf16 hi/lo planes ----------------
__global__ void split_kernel(const float* __restrict__ src, bf16* __restrict__ hi,
                             bf16* __restrict__ lo, int n4) {
    int i = blockIdx.x * blockDim.x + threadIdx.x;
    if (i >= n4) return;
    float4 v = ((const float4*)src)[i];
    u32 h0, l0, h1, l1;
    split2(v.x, v.y, h0, l0);
    split2(v.z, v.w, h1, l1);
    uint2 H; H.x = h0; H.y = h1;
    uint2 L; L.x = l0; L.y = l1;
    ((uint2*)hi)[i] = H;
    ((uint2*)lo)[i] = L;
}

// ---------------- GEMM on bf16 planes: C[M,N] = A @ W^T, bf16x3 ----------------
// CTA 128x128, BK=32, 8 warps (2x4), warp tile 64x32, 4-stage cp.async pipeline.
// SMEM plane rows: 32 bf16 data + 8 pad = 80B (ldmatrix conflict-free).
#define PLANE_B   (128 * 80)          // 10240
#define STAGE_B   (4 * PLANE_B)       // 40960
#define GEMM_SMEM (4 * STAGE_B)       // 163840

// MODE: 0 = RoPE + write hi/lo planes, 1 = write hi/lo planes, 2 = write fp32
template <int MODE>
__global__ void __launch_bounds__(256, 1)
gemm_bf(const bf16* __restrict__ Ahi, const bf16* __restrict__ Alo,
        const bf16* __restrict__ Bhi, const bf16* __restrict__ Blo,
        float* __restrict__ Cf, bf16* __restrict__ Chi, bf16* __restrict__ Clo,
        int M, int N, int K) {
    extern __shared__ char smem[];
    const u32 sb = smem_u32(smem);

    const int tid  = threadIdx.x;
    const int wid  = tid >> 5;
    const int lane = tid & 31;
    const int warp_m = (wid >> 2) * 64;
    const int warp_n = (wid & 3) * 32;

    const size_t arow0 = (size_t)blockIdx.y * 128;
    const size_t brow0 = (size_t)blockIdx.x * 128;

    const u32 a_off = (u32)(warp_m + (lane & 15)) * 80u + ((lane >> 4) * 16u);
    const u32 b_row = (u32)(warp_n + (lane & 7) + ((lane >> 4) & 1) * 8);
    const u32 b_off = b_row * 80u + ((lane >> 3) & 1) * 16u;

    float acc[4][4][4];
#pragma unroll
    for (int i = 0; i < 4; i++)
#pragma unroll
        for (int j = 0; j < 4; j++)
#pragma unroll
            for (int q = 0; q < 4; q++) acc[i][j][q] = 0.0f;

    const int NCHUNK = K >> 5;  // 64

    // cp.async loader: 2048 16B-chunks per stage, 8 per thread
    const bf16* planes[4] = {Ahi, Alo, Bhi, Blo};
    auto issue_stage = [&](int s, int ki) {
        const int kofs = ki * 32;
#pragma unroll
        for (int i = 0; i < 8; i++) {
            const int c = i * 256 + tid;
            const int pl = c >> 9;
            const int cc = c & 511;
            const int row = cc >> 2;
            const int ch = cc & 3;
            const size_t grow = (pl < 2 ? arow0 : brow0) + row;
            const bf16* src = planes[pl] + grow * K + kofs + ch * 8;
            const u32 dst = sb + s * STAGE_B + pl * PLANE_B + row * 80 + ch * 16;
            CP_ASYNC16(dst, src);
        }
    };

    issue_stage(0, 0); CP_COMMIT();
    issue_stage(1, 1); CP_COMMIT();
    issue_stage(2, 2); CP_COMMIT();

    for (int ki = 0; ki < NCHUNK; ki++) {
        CP_WAIT(2);
        __syncthreads();
        const u32 stage = sb + (u32)(ki & 3) * STAGE_B;

#pragma unroll
        for (int ks = 0; ks < 2; ks++) {
            const u32 kbyte = (u32)ks * 32u;
            u32 ah[4][4], al[4][4], bh[4][2], bl[4][2];
#pragma unroll
            for (int mt = 0; mt < 4; mt++) {
                ldmx4(ah[mt], stage + a_off + (u32)mt * (16u * 80u) + kbyte);
                ldmx4(al[mt], stage + PLANE_B + a_off + (u32)mt * (16u * 80u) + kbyte);
            }
#pragma unroll
            for (int np = 0; np < 2; np++) {
                u32 t[4];
                ldmx4(t, stage + 2 * PLANE_B + b_off + (u32)np * (16u * 80u) + kbyte);
                bh[2 * np][0] = t[0]; bh[2 * np][1] = t[1];
                bh[2 * np + 1][0] = t[2]; bh[2 * np + 1][1] = t[3];
                ldmx4(t, stage + 3 * PLANE_B + b_off + (u32)np * (16u * 80u) + kbyte);
                bl[2 * np][0] = t[0]; bl[2 * np][1] = t[1];
                bl[2 * np + 1][0] = t[2]; bl[2 * np + 1][1] = t[3];
            }
#pragma unroll
            for (int mt = 0; mt < 4; mt++)
#pragma unroll
                for (int nt = 0; nt < 4; nt++) {
                    mma16816(acc[mt][nt], ah[mt], bh[nt]);
                    mma16816(acc[mt][nt], ah[mt], bl[nt]);
                    mma16816(acc[mt][nt], al[mt], bh[nt]);
                }
        }
        if (ki + 3 < NCHUNK) issue_stage((ki + 3) & 3, ki + 3);
        CP_COMMIT();
    }

    // epilogue
    const int rbase = blockIdx.y * 128 + warp_m + (lane >> 2);
    const int cbase = blockIdx.x * 128 + warp_n + (lane & 3) * 2;
#pragma unroll
    for (int mt = 0; mt < 4; mt++) {
#pragma unroll
        for (int half = 0; half < 2; half++) {
            const int grow = rbase + mt * 16 + half * 8;
            const int t = grow & (TLEN - 1);
#pragma unroll
            for (int nt = 0; nt < 4; nt++) {
                const int gcol = cbase + nt * 8;
                float e = acc[mt][nt][half * 2 + 0];
                float o = acc[mt][nt][half * 2 + 1];
                if (MODE == 0) {
                    const int kidx = (gcol & 127) >> 1;
                    const float cs = g_cos[t * 64 + kidx];
                    const float sn = g_sin[t * 64 + kidx];
                    const float e2 = e * cs - o * sn;
                    o = e * sn + o * cs;
                    e = e2;
                }
                if (MODE <= 1) {
                    u32 hi, lo;
                    split2(e, o, hi, lo);
                    const size_t idx = ((size_t)grow * N + gcol) >> 1;
                    ((u32*)Chi)[idx] = hi;
                    ((u32*)Clo)[idx] = lo;
                } else {
                    float2 v; v.x = e; v.y = o;
                    *(float2*)(Cf + (size_t)grow * N + gcol) = v;
                }
            }
        }
    }
}

// ---------------- attention on tensor cores: one CTA per (b,h) ----------------
// smem: Khi, Klo, Vhi, Vlo planes [128 rows][272B stride] = 4 x 34816 B
#define AT_PLANE  (128 * 272)          // 34816
#define ATT_SMEM  (4 * AT_PLANE)       // 139264

__global__ void __launch_bounds__(256, 1)
attn_mma(const bf16* __restrict__ Qhi, const bf16* __restrict__ Qlo,
         const bf16* __restrict__ Khi, const bf16* __restrict__ Klo,
         const bf16* __restrict__ Vhi, const bf16* __restrict__ Vlo,
         bf16* __restrict__ Ahi, bf16* __restrict__ Alo) {
    extern __shared__ char smem[];
    const u32 sb = smem_u32(smem);
    const u32 skhi = sb;
    const u32 sklo = sb + AT_PLANE;
    const u32 svhi = sb + 2 * AT_PLANE;
    const u32 svlo = sb + 3 * AT_PLANE;

    const int bh = blockIdx.x;
    const int b = bh >> 4;
    const int h = bh & 15;
    const int tid = threadIdx.x;
    const int w = tid >> 5;
    const int l = tid & 31;

    // load K/V planes via cp.async: 4 planes x 2048 chunks / 256 thr = 32 each
    {
        const bf16* plp[4] = {Khi, Klo, Vhi, Vlo};
#pragma unroll
        for (int i = 0; i < 32; i++) {
            const int c = i * 256 + tid;
            const int pl = c >> 11;
            const int cc = c & 2047;
            const int row = cc >> 4;
            const int ch = cc & 15;
            const bf16* src = plp[pl] + ((size_t)(b * 128 + row)) * D_MODEL + h * 128 + ch * 8;
            const u32 dst = sb + pl * AT_PLANE + row * 272 + ch * 16;
            CP_ASYNC16(dst, src);
        }
        CP_COMMIT();
    }

    // Q fragments from global planes (warp w -> query rows 16w..16w+15)
    u32 aQh[8][4], aQl[8][4];
    {
        const u32* qh32 = (const u32*)Qhi;
        const u32* ql32 = (const u32*)Qlo;
        const size_t r0 = (size_t)(b * 128 + 16 * w + (l >> 2)) * (D_MODEL / 2) + h * 64 + (l & 3);
        const size_t r8 = r0 + 8 * (D_MODEL / 2);
#pragma unroll
        for (int kt = 0; kt < 8; kt++) {
            const size_t o = (size_t)kt * 8;
            aQh[kt][0] = qh32[r0 + o];     aQh[kt][1] = qh32[r8 + o];
            aQh[kt][2] = qh32[r0 + o + 4]; aQh[kt][3] = qh32[r8 + o + 4];
            aQl[kt][0] = ql32[r0 + o];     aQl[kt][1] = ql32[r8 + o];
            aQl[kt][2] = ql32[r0 + o + 4]; aQl[kt][3] = ql32[r8 + o + 4];
        }
    }
    CP_WAIT(0);
    __syncthreads();

    // ---- S = Q K^T over causal key-tiles ----
    float S[16][4];
#pragma unroll
    for (int nt = 0; nt < 16; nt++)
#pragma unroll
        for (int q = 0; q < 4; q++) S[nt][q] = 0.0f;

    const u32 kb_off = (u32)((l & 7) + 8 * ((l >> 4) & 1)) * 272u + ((l >> 3) & 1) * 16u;
#pragma unroll
    for (int np = 0; np < 8; np++) {
        if (np <= w) {
#pragma unroll
            for (int kt = 0; kt < 8; kt++) {
                u32 kh[4], kl[4];
                const u32 ro = (u32)np * (16u * 272u) + (u32)kt * 32u;
                ldmx4(kh, skhi + kb_off + ro);
                ldmx4(kl, sklo + kb_off + ro);
                u32 bh0[2] = {kh[0], kh[1]}, bh1[2] = {kh[2], kh[3]};
                u32 bl0[2] = {kl[0], kl[1]}, bl1[2] = {kl[2], kl[3]};
                mma16816(S[2 * np],     aQh[kt], bh0);
                mma16816(S[2 * np],     aQh[kt], bl0);
                mma16816(S[2 * np],     aQl[kt], bh0);
                mma16816(S[2 * np + 1], aQh[kt], bh1);
                mma16816(S[2 * np + 1], aQh[kt], bl1);
                mma16816(S[2 * np + 1], aQl[kt], bh1);
            }
        }
    }

    // ---- masked softmax in registers (rows q0 = 16w + l>>2, q1 = q0+8) ----
    const int q0 = 16 * w + (l >> 2);
    const int q1 = q0 + 8;
    const float scale = 0.08838834764831845f;  // 1/sqrt(128)
    float m0 = -1.0e30f, m1 = -1.0e30f;
#pragma unroll
    for (int nt = 0; nt < 16; nt++) {
        if (nt <= 2 * w + 1) {
            const int kc = nt * 8 + 2 * (l & 3);
            if (kc > q0)     S[nt][0] = -1.0e30f;
            if (kc + 1 > q0) S[nt][1] = -1.0e30f;
            if (kc > q1)     S[nt][2] = -1.0e30f;
            if (kc + 1 > q1) S[nt][3] = -1.0e30f;
            m0 = fmaxf(m0, fmaxf(S[nt][0], S[nt][1]));
            m1 = fmaxf(m1, fmaxf(S[nt][2], S[nt][3]));
        }
    }
    m0 = fmaxf(m0, __shfl_xor_sync(0xffffffffu, m0, 1));
    m0 = fmaxf(m0, __shfl_xor_sync(0xffffffffu, m0, 2));
    m1 = fmaxf(m1, __shfl_xor_sync(0xffffffffu, m1, 1));
    m1 = fmaxf(m1, __shfl_xor_sync(0xffffffffu, m1, 2));

    float sum0 = 0.0f, sum1 = 0.0f;
#pragma unroll
    for (int nt = 0; nt < 16; nt++) {
        if (nt <= 2 * w + 1) {
            S[nt][0] = __expf((S[nt][0] - m0) * scale);
            S[nt][1] = __expf((S[nt][1] - m0) * scale);
            S[nt][2] = __expf((S[nt][2] - m1) * scale);
            S[nt][3] = __expf((S[nt][3] - m1) * scale);
            sum0 += S[nt][0] + S[nt][1];
            sum1 += S[nt][2] + S[nt][3];
        }
    }
    sum0 += __shfl_xor_sync(0xffffffffu, sum0, 1);
    sum0 += __shfl_xor_sync(0xffffffffu, sum0, 2);
    sum1 += __shfl_xor_sync(0xffffffffu, sum1, 1);
    sum1 += __shfl_xor_sync(0xffffffffu, sum1, 2);
    const float inv0 = 1.0f / sum0;
    const float inv1 = 1.0f / sum1;

    // ---- P fragments (bf16 hi/lo) directly from acc layout ----
    u32 ph[8][4], pl[8][4];
#pragma unroll
    for (int j = 0; j < 8; j++) {
        if (j <= w) {
            split2(S[2 * j][0],     S[2 * j][1],     ph[j][0], pl[j][0]);
            split2(S[2 * j][2],     S[2 * j][3],     ph[j][1], pl[j][1]);
            split2(S[2 * j + 1][0], S[2 * j + 1][1], ph[j][2], pl[j][2]);
            split2(S[2 * j + 1][2], S[2 * j + 1][3], ph[j][3], pl[j][3]);
        }
    }

    // ---- O = P V (V via trans ldmatrix) ----
    float O[16][4];
#pragma unroll
    for (int nt = 0; nt < 16; nt++)
#pragma unroll
        for (int q = 0; q < 4; q++) O[nt][q] = 0.0f;

    const u32 vb_row = (u32)((l & 7) + 8 * ((l >> 3) & 1)) * 272u + ((l >> 4) & 1) * 16u;
#pragma unroll
    for (int j = 0; j < 8; j++) {
        if (j <= w) {
#pragma unroll
            for (int dp = 0; dp < 8; dp++) {
                u32 vh[4], vl[4];
                const u32 ro = (u32)j * (16u * 272u) + (u32)dp * 32u;
                ldmx4t(vh, svhi + vb_row + ro);
                ldmx4t(vl, svlo + vb_row + ro);
                u32 bh0[2] = {vh[0], vh[1]}, bh1[2] = {vh[2], vh[3]};
                u32 bl0[2] = {vl[0], vl[1]}, bl1[2] = {vl[2], vl[3]};
                mma16816(O[2 * dp],     ph[j], bh0);
                mma16816(O[2 * dp],     ph[j], bl0);
                mma16816(O[2 * dp],     pl[j], bh0);
                mma16816(O[2 * dp + 1], ph[j], bh1);
                mma16816(O[2 * dp + 1], ph[j], bl1);
                mma16816(O[2 * dp + 1], pl[j], bh1);
            }
        }
    }

    // ---- epilogue: normalize, split, store to attn-out planes ----
    {
        u32* ah32 = (u32*)Ahi;
        u32* al32 = (u32*)Alo;
        const size_t rA = (size_t)(b * 128 + q0) * (D_MODEL / 2) + h * 64 + (l & 3);
        const size_t rB = rA + 8 * (D_MODEL / 2);
#pragma unroll
        for (int nt = 0; nt < 16; nt++) {
            u32 hi, lo;
            split2(O[nt][0] * inv0, O[nt][1] * inv0, hi, lo);
            ah32[rA + nt * 4] = hi;
            al32[rA + nt * 4] = lo;
            split2(O[nt][2] * inv1, O[nt][3] * inv1, hi, lo);
            ah32[rB + nt * 4] = hi;
            al32[rB + nt * 4] = lo;
        }
    }
}

// ---------------- launch ----------------
extern "C" void kernel_launch(void* const* d_in, const int* in_sizes, int n_in,
                              void* d_out, int out_size) {
    const float* x  = (const float*)d_in[0];
    const float* WQ = (const float*)d_in[1];
    const float* WK = (const float*)d_in[2];
    const float* WV = (const float*)d_in[3];
    const float* WO = (const float*)d_in[4];
    float* out = (float*)d_out;

    static bf16 *xhi, *xlo, *qhi, *qlo, *khi, *klo, *vhi, *vlo, *ahi, *alo;
    static bf16 *wqhi, *wqlo, *wkhi, *wklo, *wvhi, *wvlo, *wohi, *wolo;
    static bool inited = false;
    if (!inited) {
        cudaGetSymbolAddress((void**)&xhi, g_xhi);   cudaGetSymbolAddress((void**)&xlo, g_xlo);
        cudaGetSymbolAddress((void**)&qhi, g_qhi);   cudaGetSymbolAddress((void**)&qlo, g_qlo);
        cudaGetSymbolAddress((void**)&khi, g_khi);   cudaGetSymbolAddress((void**)&klo, g_klo);
        cudaGetSymbolAddress((void**)&vhi, g_vhi);   cudaGetSymbolAddress((void**)&vlo, g_vlo);
        cudaGetSymbolAddress((void**)&ahi, g_ahi);   cudaGetSymbolAddress((void**)&alo, g_alo);
        cudaGetSymbolAddress((void**)&wqhi, g_wqhi); cudaGetSymbolAddress((void**)&wqlo, g_wqlo);
        cudaGetSymbolAddress((void**)&wkhi, g_wkhi); cudaGetSymbolAddress((void**)&wklo, g_wklo);
        cudaGetSymbolAddress((void**)&wvhi, g_wvhi); cudaGetSymbolAddress((void**)&wvlo, g_wvlo);
        cudaGetSymbolAddress((void**)&wohi, g_wohi); cudaGetSymbolAddress((void**)&wolo, g_wolo);
        cudaFuncSetAttribute(gemm_bf<0>, cudaFuncAttributeMaxDynamicSharedMemorySize, GEMM_SMEM);
        cudaFuncSetAttribute(gemm_bf<1>, cudaFuncAttributeMaxDynamicSharedMemorySize, GEMM_SMEM);
        cudaFuncSetAttribute(gemm_bf<2>, cudaFuncAttributeMaxDynamicSharedMemorySize, GEMM_SMEM);
        cudaFuncSetAttribute(attn_mma, cudaFuncAttributeMaxDynamicSharedMemorySize, ATT_SMEM);
        inited = true;
    }

    rope_init_kernel<<<32, 256>>>();

    const int nx4 = NROWS * D_MODEL / 4;
    const int nw4 = D_MODEL * D_MODEL / 4;
    split_kernel<<<(nx4 + 255) / 256, 256>>>(x,  xhi,  xlo,  nx4);
    split_kernel<<<(nw4 + 255) / 256, 256>>>(WQ, wqhi, wqlo, nw4);
    split_kernel<<<(nw4 + 255) / 256, 256>>>(WK, wkhi, wklo, nw4);
    split_kernel<<<(nw4 + 255) / 256, 256>>>(WV, wvhi, wvlo, nw4);
    split_kernel<<<(nw4 + 255) / 256, 256>>>(WO, wohi, wolo, nw4);

    dim3 grid(D_MODEL / 128, NROWS / 128);   // (16, 64)
    dim3 blk(256);
    gemm_bf<0><<<grid, blk, GEMM_SMEM>>>(xhi, xlo, wqhi, wqlo, nullptr, qhi, qlo,
                                         NROWS, D_MODEL, D_MODEL);
    gemm_bf<0><<<grid, blk, GEMM_SMEM>>>(xhi, xlo, wkhi, wklo, nullptr, khi, klo,
                                         NROWS, D_MODEL, D_MODEL);
    gemm_bf<1><<<grid, blk, GEMM_SMEM>>>(xhi, xlo, wvhi, wvlo, nullptr, vhi, vlo,
                                         NROWS, D_MODEL, D_MODEL);

    attn_mma<<<BATCH * NHEADS, 256, ATT_SMEM>>>(qhi, qlo, khi, klo, vhi, vlo, ahi, alo);

    gemm_bf<2><<<grid, blk, GEMM_SMEM>>>(ahi, alo, wohi, wolo, out, nullptr, nullptr,
                                         NROWS, D_MODEL, D_MODEL);
}

// round 5
// speedup vs baseline: 2.9125x; 1.0119x over previous
#include <cuda_runtime.h>
#include <cuda_bf16.h>
#include <cstdint>
#include <math.h>

#define D_MODEL 2048
#define NHEADS  16
#define DHEAD   128
#define BATCH   64
#define TLEN    128
#define NROWS   (BATCH * TLEN)   // 8192

typedef __nv_bfloat16 bf16;
typedef uint32_t u32;

// ---------------- bf16 hi/lo plane scratch ----------------
__device__ bf16 g_xhi[(size_t)NROWS * D_MODEL];
__device__ bf16 g_xlo[(size_t)NROWS * D_MODEL];
__device__ bf16 g_qhi[(size_t)NROWS * D_MODEL];
__device__ bf16 g_qlo[(size_t)NROWS * D_MODEL];
__device__ bf16 g_khi[(size_t)NROWS * D_MODEL];
__device__ bf16 g_klo[(size_t)NROWS * D_MODEL];
__device__ bf16 g_vhi[(size_t)NROWS * D_MODEL];
__device__ bf16 g_vlo[(size_t)NROWS * D_MODEL];
__device__ bf16 g_ahi[(size_t)NROWS * D_MODEL];
__device__ bf16 g_alo[(size_t)NROWS * D_MODEL];
__device__ bf16 g_wqhi[(size_t)D_MODEL * D_MODEL];
__device__ bf16 g_wqlo[(size_t)D_MODEL * D_MODEL];
__device__ bf16 g_wkhi[(size_t)D_MODEL * D_MODEL];
__device__ bf16 g_wklo[(size_t)D_MODEL * D_MODEL];
__device__ bf16 g_wvhi[(size_t)D_MODEL * D_MODEL];
__device__ bf16 g_wvlo[(size_t)D_MODEL * D_MODEL];
__device__ bf16 g_wohi[(size_t)D_MODEL * D_MODEL];
__device__ bf16 g_wolo[(size_t)D_MODEL * D_MODEL];
__device__ float g_cos[TLEN * 64];
__device__ float g_sin[TLEN * 64];

// ---------------- primitives ----------------
__device__ __forceinline__ void mma16816(float* c, const u32* a, const u32* b) {
    asm volatile(
        "mma.sync.aligned.m16n8k16.row.col.f32.bf16.bf16.f32 "
        "{%0,%1,%2,%3}, {%4,%5,%6,%7}, {%8,%9}, {%0,%1,%2,%3};"
        : "+f"(c[0]), "+f"(c[1]), "+f"(c[2]), "+f"(c[3])
        : "r"(a[0]), "r"(a[1]), "r"(a[2]), "r"(a[3]), "r"(b[0]), "r"(b[1]));
}
__device__ __forceinline__ void ldmx4(u32* r, u32 addr) {
    asm volatile("ldmatrix.sync.aligned.m8n8.x4.shared.b16 {%0,%1,%2,%3}, [%4];"
                 : "=r"(r[0]), "=r"(r[1]), "=r"(r[2]), "=r"(r[3]) : "r"(addr));
}
__device__ __forceinline__ void ldmx4t(u32* r, u32 addr) {
    asm volatile("ldmatrix.sync.aligned.m8n8.x4.trans.shared.b16 {%0,%1,%2,%3}, [%4];"
                 : "=r"(r[0]), "=r"(r[1]), "=r"(r[2]), "=r"(r[3]) : "r"(addr));
}
__device__ __forceinline__ u32 smem_u32(const void* p) {
    return (u32)__cvta_generic_to_shared(p);
}
#define CP_ASYNC16(dst, src) \
    asm volatile("cp.async.cg.shared.global [%0], [%1], 16;" :: "r"(dst), "l"(src))
#define CP_COMMIT() asm volatile("cp.async.commit_group;" ::: "memory")
#define CP_WAIT(n)  asm volatile("cp.async.wait_group %0;" :: "n"(n) : "memory")

__device__ __forceinline__ u32 packbf(bf16 a, bf16 b) {
    __nv_bfloat162 h; h.x = a; h.y = b;
    return *(u32*)&h;
}
__device__ __forceinline__ void split2(float e, float o, u32& hi, u32& lo) {
    bf16 eh = __float2bfloat16_rn(e);
    bf16 oh = __float2bfloat16_rn(o);
    float er = e - __bfloat162float(eh);
    float orr = o - __bfloat162float(oh);
    hi = packbf(eh, oh);
    lo = packbf(__float2bfloat16_rn(er), __float2bfloat16_rn(orr));
}

// ---------------- RoPE table ----------------
__global__ void rope_init_kernel() {
    int idx = blockIdx.x * blockDim.x + threadIdx.x;
    if (idx >= TLEN * 64) return;
    int t = idx >> 6;
    int k = idx & 63;
    double theta = exp(-(double)k * (9.210340371976184 / 64.0));
    double ang = (double)t * theta;
    g_cos[idx] = (float)cos(ang);
    g_sin[idx] = (float)sin(ang);
}

// ---------------- fused split: x + 4 weights in one launch ----------------
#define NX4 (NROWS * D_MODEL / 4)      // 4194304
#define NW4 (D_MODEL * D_MODEL / 4)    // 1048576
__global__ void split_all(const float* __restrict__ x,  const float* __restrict__ wq,
                          const float* __restrict__ wk, const float* __restrict__ wv,
                          const float* __restrict__ wo,
                          bf16* xhi, bf16* xlo, bf16* qhi, bf16* qlo,
                          bf16* khi, bf16* klo, bf16* vhi, bf16* vlo,
                          bf16* ohi, bf16* olo) {
    int i = blockIdx.x * blockDim.x + threadIdx.x;
    const float* src;
    bf16 *hi, *lo;
    int j;
    if (i < NX4) {
        src = x; hi = xhi; lo = xlo; j = i;
    } else {
        int r = i - NX4;
        int region = r / NW4;
        j = r - region * NW4;
        switch (region) {
            case 0:  src = wq; hi = qhi; lo = qlo; break;
            case 1:  src = wk; hi = khi; lo = klo; break;
            case 2:  src = wv; hi = vhi; lo = vlo; break;
            default: src = wo; hi = ohi; lo = olo; break;
        }
    }
    float4 v = ((const float4*)src)[j];
    u32 h0, l0, h1, l1;
    split2(v.x, v.y, h0, l0);
    split2(v.z, v.w, h1, l1);
    uint2 H; H.x = h0; H.y = h1;
    uint2 L; L.x = l0; L.y = l1;
    ((uint2*)hi)[j] = H;
    ((uint2*)lo)[j] = L;
}

// ---------------- GEMM mainloop (shared device body) ----------------
// CTA 128x128, BK=32, 8 warps (2x4), warp tile 64x32, 4-stage cp.async pipeline.
#define PLANE_B   (128 * 80)          // 10240
#define STAGE_B   (4 * PLANE_B)       // 40960
#define GEMM_SMEM (4 * STAGE_B)       // 163840

struct AccT { float a[4][4][4]; };

__device__ __forceinline__ void gemm_mainloop(
    const bf16* __restrict__ Ahi, const bf16* __restrict__ Alo,
    const bf16* __restrict__ Bhi, const bf16* __restrict__ Blo,
    size_t arow0, size_t brow0, int K, AccT& A) {
    extern __shared__ char smem[];
    const u32 sb = smem_u32(smem);
    const int tid  = threadIdx.x;
    const int wid  = tid >> 5;
    const int lane = tid & 31;
    const int warp_m = (wid >> 2) * 64;
    const int warp_n = (wid & 3) * 32;

    const u32 a_off = (u32)(warp_m + (lane & 15)) * 80u + ((lane >> 4) * 16u);
    const u32 b_row = (u32)(warp_n + (lane & 7) + ((lane >> 4) & 1) * 8);
    const u32 b_off = b_row * 80u + ((lane >> 3) & 1) * 16u;

#pragma unroll
    for (int i = 0; i < 4; i++)
#pragma unroll
        for (int j = 0; j < 4; j++)
#pragma unroll
            for (int q = 0; q < 4; q++) A.a[i][j][q] = 0.0f;

    const int NCHUNK = K >> 5;  // 64
    const bf16* planes[4] = {Ahi, Alo, Bhi, Blo};
    auto issue_stage = [&](int s, int ki) {
        const int kofs = ki * 32;
#pragma unroll
        for (int i = 0; i < 8; i++) {
            const int c = i * 256 + tid;
            const int pl = c >> 9;
            const int cc = c & 511;
            const int row = cc >> 2;
            const int ch = cc & 3;
            const size_t grow = (pl < 2 ? arow0 : brow0) + row;
            const bf16* src = planes[pl] + grow * K + kofs + ch * 8;
            const u32 dst = sb + s * STAGE_B + pl * PLANE_B + row * 80 + ch * 16;
            CP_ASYNC16(dst, src);
        }
    };

    issue_stage(0, 0); CP_COMMIT();
    issue_stage(1, 1); CP_COMMIT();
    issue_stage(2, 2); CP_COMMIT();

    for (int ki = 0; ki < NCHUNK; ki++) {
        CP_WAIT(2);
        __syncthreads();
        const u32 stage = sb + (u32)(ki & 3) * STAGE_B;

#pragma unroll
        for (int ks = 0; ks < 2; ks++) {
            const u32 kbyte = (u32)ks * 32u;
            u32 ah[4][4], al[4][4], bh[4][2], bl[4][2];
#pragma unroll
            for (int mt = 0; mt < 4; mt++) {
                ldmx4(ah[mt], stage + a_off + (u32)mt * (16u * 80u) + kbyte);
                ldmx4(al[mt], stage + PLANE_B + a_off + (u32)mt * (16u * 80u) + kbyte);
            }
#pragma unroll
            for (int np = 0; np < 2; np++) {
                u32 t[4];
                ldmx4(t, stage + 2 * PLANE_B + b_off + (u32)np * (16u * 80u) + kbyte);
                bh[2 * np][0] = t[0]; bh[2 * np][1] = t[1];
                bh[2 * np + 1][0] = t[2]; bh[2 * np + 1][1] = t[3];
                ldmx4(t, stage + 3 * PLANE_B + b_off + (u32)np * (16u * 80u) + kbyte);
                bl[2 * np][0] = t[0]; bl[2 * np][1] = t[1];
                bl[2 * np + 1][0] = t[2]; bl[2 * np + 1][1] = t[3];
            }
            // pass-major: same accumulator revisited only every 16 MMAs
#pragma unroll
            for (int pass = 0; pass < 3; pass++)
#pragma unroll
                for (int mt = 0; mt < 4; mt++)
#pragma unroll
                    for (int nt = 0; nt < 4; nt++)
                        mma16816(A.a[mt][nt],
                                 pass == 2 ? al[mt] : ah[mt],
                                 pass == 1 ? bl[nt] : bh[nt]);
        }
        if (ki + 3 < NCHUNK) issue_stage((ki + 3) & 3, ki + 3);
        CP_COMMIT();
    }
}

// ---------------- fused QKV GEMM (gridDim.z = 3) ----------------
__global__ void __launch_bounds__(256, 1)
gemm_qkv(const bf16* __restrict__ Xhi, const bf16* __restrict__ Xlo,
         const bf16* __restrict__ WQh, const bf16* __restrict__ WQl,
         const bf16* __restrict__ WKh, const bf16* __restrict__ WKl,
         const bf16* __restrict__ WVh, const bf16* __restrict__ WVl,
         bf16* __restrict__ Qh, bf16* __restrict__ Ql,
         bf16* __restrict__ Kh, bf16* __restrict__ Kl,
         bf16* __restrict__ Vh, bf16* __restrict__ Vl) {
    const int z = blockIdx.z;
    const bf16 *Bhi, *Blo;
    bf16 *Chi, *Clo;
    if (z == 0)      { Bhi = WQh; Blo = WQl; Chi = Qh; Clo = Ql; }
    else if (z == 1) { Bhi = WKh; Blo = WKl; Chi = Kh; Clo = Kl; }
    else             { Bhi = WVh; Blo = WVl; Chi = Vh; Clo = Vl; }
    const bool rope = (z < 2);

    AccT A;
    gemm_mainloop(Xhi, Xlo, Bhi, Blo,
                  (size_t)blockIdx.y * 128, (size_t)blockIdx.x * 128, D_MODEL, A);

    const int tid  = threadIdx.x;
    const int wid  = tid >> 5;
    const int lane = tid & 31;
    const int warp_m = (wid >> 2) * 64;
    const int warp_n = (wid & 3) * 32;
    const int rbase = blockIdx.y * 128 + warp_m + (lane >> 2);
    const int cbase = blockIdx.x * 128 + warp_n + (lane & 3) * 2;
#pragma unroll
    for (int mt = 0; mt < 4; mt++) {
#pragma unroll
        for (int half = 0; half < 2; half++) {
            const int grow = rbase + mt * 16 + half * 8;
            const int t = grow & (TLEN - 1);
#pragma unroll
            for (int nt = 0; nt < 4; nt++) {
                const int gcol = cbase + nt * 8;
                float e = A.a[mt][nt][half * 2 + 0];
                float o = A.a[mt][nt][half * 2 + 1];
                if (rope) {
                    const int kidx = (gcol & 127) >> 1;
                    const float cs = g_cos[t * 64 + kidx];
                    const float sn = g_sin[t * 64 + kidx];
                    const float e2 = e * cs - o * sn;
                    o = e * sn + o * cs;
                    e = e2;
                }
                u32 hi, lo;
                split2(e, o, hi, lo);
                const size_t idx = ((size_t)grow * D_MODEL + gcol) >> 1;
                ((u32*)Chi)[idx] = hi;
                ((u32*)Clo)[idx] = lo;
            }
        }
    }
}

// ---------------- output GEMM (fp32 out) ----------------
__global__ void __launch_bounds__(256, 1)
gemm_out(const bf16* __restrict__ Ahi, const bf16* __restrict__ Alo,
         const bf16* __restrict__ Bhi, const bf16* __restrict__ Blo,
         float* __restrict__ Cf) {
    AccT A;
    gemm_mainloop(Ahi, Alo, Bhi, Blo,
                  (size_t)blockIdx.y * 128, (size_t)blockIdx.x * 128, D_MODEL, A);

    const int tid  = threadIdx.x;
    const int wid  = tid >> 5;
    const int lane = tid & 31;
    const int warp_m = (wid >> 2) * 64;
    const int warp_n = (wid & 3) * 32;
    const int rbase = blockIdx.y * 128 + warp_m + (lane >> 2);
    const int cbase = blockIdx.x * 128 + warp_n + (lane & 3) * 2;
#pragma unroll
    for (int mt = 0; mt < 4; mt++)
#pragma unroll
        for (int half = 0; half < 2; half++) {
            const int grow = rbase + mt * 16 + half * 8;
#pragma unroll
            for (int nt = 0; nt < 4; nt++) {
                const int gcol = cbase + nt * 8;
                float2 v;
                v.x = A.a[mt][nt][half * 2 + 0];
                v.y = A.a[mt][nt][half * 2 + 1];
                *(float2*)(Cf + (size_t)grow * D_MODEL + gcol) = v;
            }
        }
}

// ---------------- attention on tensor cores: one CTA per (b,h) ----------------
#define AT_PLANE  (128 * 272)          // 34816
#define ATT_SMEM  (4 * AT_PLANE)       // 139264

__global__ void __launch_bounds__(256, 1)
attn_mma(const bf16* __restrict__ Qhi, const bf16* __restrict__ Qlo,
         const bf16* __restrict__ Khi, const bf16* __restrict__ Klo,
         const bf16* __restrict__ Vhi, const bf16* __restrict__ Vlo,
         bf16* __restrict__ Ahi, bf16* __restrict__ Alo) {
    extern __shared__ char smem[];
    const u32 sb = smem_u32(smem);
    const u32 skhi = sb;
    const u32 sklo = sb + AT_PLANE;
    const u32 svhi = sb + 2 * AT_PLANE;
    const u32 svlo = sb + 3 * AT_PLANE;

    const int bh = blockIdx.x;
    const int b = bh >> 4;
    const int h = bh & 15;
    const int tid = threadIdx.x;
    const int w = tid >> 5;
    const int l = tid & 31;

    {
        const bf16* plp[4] = {Khi, Klo, Vhi, Vlo};
#pragma unroll
        for (int i = 0; i < 32; i++) {
            const int c = i * 256 + tid;
            const int pl = c >> 11;
            const int cc = c & 2047;
            const int row = cc >> 4;
            const int ch = cc & 15;
            const bf16* src = plp[pl] + ((size_t)(b * 128 + row)) * D_MODEL + h * 128 + ch * 8;
            const u32 dst = sb + pl * AT_PLANE + row * 272 + ch * 16;
            CP_ASYNC16(dst, src);
        }
        CP_COMMIT();
    }

    u32 aQh[8][4], aQl[8][4];
    {
        const u32* qh32 = (const u32*)Qhi;
        const u32* ql32 = (const u32*)Qlo;
        const size_t r0 = (size_t)(b * 128 + 16 * w + (l >> 2)) * (D_MODEL / 2) + h * 64 + (l & 3);
        const size_t r8 = r0 + 8 * (D_MODEL / 2);
#pragma unroll
        for (int kt = 0; kt < 8; kt++) {
            const size_t o = (size_t)kt * 8;
            aQh[kt][0] = qh32[r0 + o];     aQh[kt][1] = qh32[r8 + o];
            aQh[kt][2] = qh32[r0 + o + 4]; aQh[kt][3] = qh32[r8 + o + 4];
            aQl[kt][0] = ql32[r0 + o];     aQl[kt][1] = ql32[r8 + o];
            aQl[kt][2] = ql32[r0 + o + 4]; aQl[kt][3] = ql32[r8 + o + 4];
        }
    }
    CP_WAIT(0);
    __syncthreads();

    // ---- S = Q K^T over causal key-tiles ----
    float S[16][4];
#pragma unroll
    for (int nt = 0; nt < 16; nt++)
#pragma unroll
        for (int q = 0; q < 4; q++) S[nt][q] = 0.0f;

    const u32 kb_off = (u32)((l & 7) + 8 * ((l >> 4) & 1)) * 272u + ((l >> 3) & 1) * 16u;
#pragma unroll
    for (int np = 0; np < 8; np++) {
        if (np <= w) {
#pragma unroll
            for (int kt = 0; kt < 8; kt++) {
                u32 kh[4], kl[4];
                const u32 ro = (u32)np * (16u * 272u) + (u32)kt * 32u;
                ldmx4(kh, skhi + kb_off + ro);
                ldmx4(kl, sklo + kb_off + ro);
                u32 bh0[2] = {kh[0], kh[1]}, bh1[2] = {kh[2], kh[3]};
                u32 bl0[2] = {kl[0], kl[1]}, bl1[2] = {kl[2], kl[3]};
                // pass-major, alternate accs
                mma16816(S[2 * np],     aQh[kt], bh0);
                mma16816(S[2 * np + 1], aQh[kt], bh1);
                mma16816(S[2 * np],     aQh[kt], bl0);
                mma16816(S[2 * np + 1], aQh[kt], bl1);
                mma16816(S[2 * np],     aQl[kt], bh0);
                mma16816(S[2 * np + 1], aQl[kt], bh1);
            }
        }
    }

    // ---- masked softmax in registers ----
    const int q0 = 16 * w + (l >> 2);
    const int q1 = q0 + 8;
    const float scale = 0.08838834764831845f;
    float m0 = -1.0e30f, m1 = -1.0e30f;
#pragma unroll
    for (int nt = 0; nt < 16; nt++) {
        if (nt <= 2 * w + 1) {
            const int kc = nt * 8 + 2 * (l & 3);
            if (kc > q0)     S[nt][0] = -1.0e30f;
            if (kc + 1 > q0) S[nt][1] = -1.0e30f;
            if (kc > q1)     S[nt][2] = -1.0e30f;
            if (kc + 1 > q1) S[nt][3] = -1.0e30f;
            m0 = fmaxf(m0, fmaxf(S[nt][0], S[nt][1]));
            m1 = fmaxf(m1, fmaxf(S[nt][2], S[nt][3]));
        }
    }
    m0 = fmaxf(m0, __shfl_xor_sync(0xffffffffu, m0, 1));
    m0 = fmaxf(m0, __shfl_xor_sync(0xffffffffu, m0, 2));
    m1 = fmaxf(m1, __shfl_xor_sync(0xffffffffu, m1, 1));
    m1 = fmaxf(m1, __shfl_xor_sync(0xffffffffu, m1, 2));

    float sum0 = 0.0f, sum1 = 0.0f;
#pragma unroll
    for (int nt = 0; nt < 16; nt++) {
        if (nt <= 2 * w + 1) {
            S[nt][0] = __expf((S[nt][0] - m0) * scale);
            S[nt][1] = __expf((S[nt][1] - m0) * scale);
            S[nt][2] = __expf((S[nt][2] - m1) * scale);
            S[nt][3] = __expf((S[nt][3] - m1) * scale);
            sum0 += S[nt][0] + S[nt][1];
            sum1 += S[nt][2] + S[nt][3];
        }
    }
    sum0 += __shfl_xor_sync(0xffffffffu, sum0, 1);
    sum0 += __shfl_xor_sync(0xffffffffu, sum0, 2);
    sum1 += __shfl_xor_sync(0xffffffffu, sum1, 1);
    sum1 += __shfl_xor_sync(0xffffffffu, sum1, 2);
    const float inv0 = 1.0f / sum0;
    const float inv1 = 1.0f / sum1;

    // ---- P fragments ----
    u32 ph[8][4], pl[8][4];
#pragma unroll
    for (int j = 0; j < 8; j++) {
        if (j <= w) {
            split2(S[2 * j][0],     S[2 * j][1],     ph[j][0], pl[j][0]);
            split2(S[2 * j][2],     S[2 * j][3],     ph[j][1], pl[j][1]);
            split2(S[2 * j + 1][0], S[2 * j + 1][1], ph[j][2], pl[j][2]);
            split2(S[2 * j + 1][2], S[2 * j + 1][3], ph[j][3], pl[j][3]);
        }
    }

    // ---- O = P V, dp-paired pass-major (acc reuse distance 4) ----
    float O[16][4];
#pragma unroll
    for (int nt = 0; nt < 16; nt++)
#pragma unroll
        for (int q = 0; q < 4; q++) O[nt][q] = 0.0f;

    const u32 vb_row = (u32)((l & 7) + 8 * ((l >> 3) & 1)) * 272u + ((l >> 4) & 1) * 16u;
#pragma unroll
    for (int j = 0; j < 8; j++) {
        if (j <= w) {
#pragma unroll
            for (int dp = 0; dp < 8; dp += 2) {
                u32 vh0[4], vl0[4], vh1[4], vl1[4];
                const u32 ro0 = (u32)j * (16u * 272u) + (u32)dp * 32u;
                const u32 ro1 = ro0 + 32u;
                ldmx4t(vh0, svhi + vb_row + ro0);
                ldmx4t(vl0, svlo + vb_row + ro0);
                ldmx4t(vh1, svhi + vb_row + ro1);
                ldmx4t(vl1, svlo + vb_row + ro1);
                u32 h00[2] = {vh0[0], vh0[1]}, h01[2] = {vh0[2], vh0[3]};
                u32 l00[2] = {vl0[0], vl0[1]}, l01[2] = {vl0[2], vl0[3]};
                u32 h10[2] = {vh1[0], vh1[1]}, h11[2] = {vh1[2], vh1[3]};
                u32 l10[2] = {vl1[0], vl1[1]}, l11[2] = {vl1[2], vl1[3]};
                float* O0 = O[2 * dp];
                float* O1 = O[2 * dp + 1];
                float* O2 = O[2 * dp + 2];
                float* O3 = O[2 * dp + 3];
                mma16816(O0, ph[j], h00); mma16816(O1, ph[j], h01);
                mma16816(O2, ph[j], h10); mma16816(O3, ph[j], h11);
                mma16816(O0, ph[j], l00); mma16816(O1, ph[j], l01);
                mma16816(O2, ph[j], l10); mma16816(O3, ph[j], l11);
                mma16816(O0, pl[j], h00); mma16816(O1, pl[j], h01);
                mma16816(O2, pl[j], h10); mma16816(O3, pl[j], h11);
            }
        }
    }

    // ---- epilogue ----
    {
        u32* ah32 = (u32*)Ahi;
        u32* al32 = (u32*)Alo;
        const size_t rA = (size_t)(b * 128 + q0) * (D_MODEL / 2) + h * 64 + (l & 3);
        const size_t rB = rA + 8 * (D_MODEL / 2);
#pragma unroll
        for (int nt = 0; nt < 16; nt++) {
            u32 hi, lo;
            split2(O[nt][0] * inv0, O[nt][1] * inv0, hi, lo);
            ah32[rA + nt * 4] = hi;
            al32[rA + nt * 4] = lo;
            split2(O[nt][2] * inv1, O[nt][3] * inv1, hi, lo);
            ah32[rB + nt * 4] = hi;
            al32[rB + nt * 4] = lo;
        }
    }
}

// ---------------- launch ----------------
extern "C" void kernel_launch(void* const* d_in, const int* in_sizes, int n_in,
                              void* d_out, int out_size) {
    const float* x  = (const float*)d_in[0];
    const float* WQ = (const float*)d_in[1];
    const float* WK = (const float*)d_in[2];
    const float* WV = (const float*)d_in[3];
    const float* WO = (const float*)d_in[4];
    float* out = (float*)d_out;

    static bf16 *xhi, *xlo, *qhi, *qlo, *khi, *klo, *vhi, *vlo, *ahi, *alo;
    static bf16 *wqhi, *wqlo, *wkhi, *wklo, *wvhi, *wvlo, *wohi, *wolo;
    static bool inited = false;
    if (!inited) {
        cudaGetSymbolAddress((void**)&xhi, g_xhi);   cudaGetSymbolAddress((void**)&xlo, g_xlo);
        cudaGetSymbolAddress((void**)&qhi, g_qhi);   cudaGetSymbolAddress((void**)&qlo, g_qlo);
        cudaGetSymbolAddress((void**)&khi, g_khi);   cudaGetSymbolAddress((void**)&klo, g_klo);
        cudaGetSymbolAddress((void**)&vhi, g_vhi);   cudaGetSymbolAddress((void**)&vlo, g_vlo);
        cudaGetSymbolAddress((void**)&ahi, g_ahi);   cudaGetSymbolAddress((void**)&alo, g_alo);
        cudaGetSymbolAddress((void**)&wqhi, g_wqhi); cudaGetSymbolAddress((void**)&wqlo, g_wqlo);
        cudaGetSymbolAddress((void**)&wkhi, g_wkhi); cudaGetSymbolAddress((void**)&wklo, g_wklo);
        cudaGetSymbolAddress((void**)&wvhi, g_wvhi); cudaGetSymbolAddress((void**)&wvlo, g_wvlo);
        cudaGetSymbolAddress((void**)&wohi, g_wohi); cudaGetSymbolAddress((void**)&wolo, g_wolo);
        cudaFuncSetAttribute(gemm_qkv, cudaFuncAttributeMaxDynamicSharedMemorySize, GEMM_SMEM);
        cudaFuncSetAttribute(gemm_out, cudaFuncAttributeMaxDynamicSharedMemorySize, GEMM_SMEM);
        cudaFuncSetAttribute(attn_mma, cudaFuncAttributeMaxDynamicSharedMemorySize, ATT_SMEM);
        inited = true;
    }

    rope_init_kernel<<<32, 256>>>();

    const int ntot = NX4 + 4 * NW4;
    split_all<<<(ntot + 255) / 256, 256>>>(x, WQ, WK, WV, WO,
                                           xhi, xlo, wqhi, wqlo, wkhi, wklo,
                                           wvhi, wvlo, wohi, wolo);

    dim3 gq(D_MODEL / 128, NROWS / 128, 3);   // (16, 64, 3)
    dim3 blk(256);
    gemm_qkv<<<gq, blk, GEMM_SMEM>>>(xhi, xlo, wqhi, wqlo, wkhi, wklo, wvhi, wvlo,
                                     qhi, qlo, khi, klo, vhi, vlo);

    attn_mma<<<BATCH * NHEADS, 256, ATT_SMEM>>>(qhi, qlo, khi, klo, vhi, vlo, ahi, alo);

    dim3 go(D_MODEL / 128, NROWS / 128);
    gemm_out<<<go, blk, GEMM_SMEM>>>(ahi, alo, wohi, wolo, out);
}